// round 1
// baseline (speedup 1.0000x reference)
#include <cuda_runtime.h>
#include <cuda_bf16.h>
#include <math.h>

// ---------------- constants ----------------
#define BB 4
#define NN 4096
#define CC 256
#define HEADS 8
#define HD 32
#define SR 2
#define HH 64
#define WW 64
#define NKV 1024            // (64/2)*(64/2)
#define EPS 1e-5f

// ---------------- scratch (device globals: no allocation allowed) ----------------
__device__ float g_q[BB * NN * CC];          // 16 MB  [b, n, h*32+d]
__device__ float g_im2col[BB * NKV * 1024];  // 16 MB  [b*t, ci*4+kh*2+kw]
__device__ float g_xsr[BB * NKV * CC];       //  4 MB  [b, t, c]  (post-LN, in place)
__device__ float g_kv[BB * NKV * 512];       //  8 MB  [b, t, (which*8+h)*32+d]
__device__ float g_attn[BB * NN * CC];       // 16 MB  [b, n, h*32+d]

// ---------------- generic tiled fp32 GEMM: C[M,N] = A[M,K] @ B[N,K]^T + bias[N] ----------------
// BM=BN=64, BK=16, 256 threads, 4x4 per thread. Requires M%64==0, N%64==0, K%16==0.
__global__ void gemm_bt_kernel(const float* __restrict__ A,
                               const float* __restrict__ B,
                               const float* __restrict__ bias,
                               float* __restrict__ C,
                               int M, int N, int K)
{
    const int BM = 64, BN = 64, BK = 16;
    __shared__ float As[BK][BM];
    __shared__ float Bs[BK][BN];

    int tid = threadIdx.x;           // 0..255
    int tx  = tid & 15;              // 0..15
    int ty  = tid >> 4;              // 0..15
    int rowBase = blockIdx.y * BM;
    int colBase = blockIdx.x * BN;

    float acc[4][4];
#pragma unroll
    for (int i = 0; i < 4; i++)
#pragma unroll
        for (int j = 0; j < 4; j++) acc[i][j] = 0.f;

    int lr = tid >> 2;       // 0..63 row within tile
    int lc = tid & 3;        // float4 index within 16-wide K slab

    for (int k0 = 0; k0 < K; k0 += BK) {
        float4 a = *(const float4*)&A[(size_t)(rowBase + lr) * K + k0 + lc * 4];
        As[lc * 4 + 0][lr] = a.x;
        As[lc * 4 + 1][lr] = a.y;
        As[lc * 4 + 2][lr] = a.z;
        As[lc * 4 + 3][lr] = a.w;
        float4 bv = *(const float4*)&B[(size_t)(colBase + lr) * K + k0 + lc * 4];
        Bs[lc * 4 + 0][lr] = bv.x;
        Bs[lc * 4 + 1][lr] = bv.y;
        Bs[lc * 4 + 2][lr] = bv.z;
        Bs[lc * 4 + 3][lr] = bv.w;
        __syncthreads();

#pragma unroll
        for (int k = 0; k < BK; k++) {
            float ar[4], br[4];
#pragma unroll
            for (int i = 0; i < 4; i++) ar[i] = As[k][ty * 4 + i];
#pragma unroll
            for (int j = 0; j < 4; j++) br[j] = Bs[k][tx * 4 + j];
#pragma unroll
            for (int i = 0; i < 4; i++)
#pragma unroll
                for (int j = 0; j < 4; j++) acc[i][j] += ar[i] * br[j];
        }
        __syncthreads();
    }

#pragma unroll
    for (int i = 0; i < 4; i++) {
        int r = rowBase + ty * 4 + i;
#pragma unroll
        for (int j = 0; j < 4; j++) {
            int c = colBase + tx * 4 + j;
            C[(size_t)r * N + c] = acc[i][j] + bias[c];
        }
    }
}

// ---------------- im2col for 2x2 stride-2 conv ----------------
// g_im2col[(b*1024+t), ci*4 + kh*2 + kw] = x[b, (2i+kh)*64 + 2j+kw, ci], t = i*32+j
__global__ void im2col_kernel(const float* __restrict__ x)
{
    int idx = blockIdx.x * blockDim.x + threadIdx.x;   // 0 .. 4M-1
    int col = idx & 1023;
    int bt  = idx >> 10;
    int b = bt >> 10;
    int t = bt & 1023;
    int i = t >> 5, j = t & 31;
    int ci = col >> 2;
    int kh = (col >> 1) & 1;
    int kw = col & 1;
    int y  = 2 * i + kh;
    int xx = 2 * j + kw;
    g_im2col[idx] = x[((size_t)b * NN + y * WW + xx) * CC + ci];
}

// ---------------- LayerNorm over C=256, one block per token ----------------
__global__ void ln_kernel(const float* __restrict__ g, const float* __restrict__ bta)
{
    __shared__ float sbuf[256];
    int t = blockIdx.x;          // 0..4095 (b*1024+t)
    int c = threadIdx.x;
    float v = g_xsr[(size_t)t * CC + c];

    sbuf[c] = v;
    __syncthreads();
    for (int s = 128; s > 0; s >>= 1) {
        if (c < s) sbuf[c] += sbuf[c + s];
        __syncthreads();
    }
    float mu = sbuf[0] * (1.f / CC);
    __syncthreads();
    float d = v - mu;
    sbuf[c] = d * d;
    __syncthreads();
    for (int s = 128; s > 0; s >>= 1) {
        if (c < s) sbuf[c] += sbuf[c + s];
        __syncthreads();
    }
    float var = sbuf[0] * (1.f / CC);
    float r = rsqrtf(var + EPS);
    g_xsr[(size_t)t * CC + c] = d * r * g[c] + bta[c];
}

// ---------------- fused attention (online softmax), 1 thread = 1 query row ----------------
#define TKV 128
__global__ void attn_kernel()
{
    __shared__ float4 sK[TKV * 8];
    __shared__ float4 sV[TKV * 8];

    const float scale = 0.17677669529663687f;   // 32^-0.5
    int b  = blockIdx.z;
    int hh = blockIdx.y;
    int qi = blockIdx.x * 256 + threadIdx.x;

    float4 q4[8];
    const float4* qp = (const float4*)&g_q[((size_t)b * NN + qi) * CC + hh * HD];
#pragma unroll
    for (int i = 0; i < 8; i++) q4[i] = qp[i];

    float m = -1e30f, l = 0.f;
    float4 acc[8];
#pragma unroll
    for (int i = 0; i < 8; i++) acc[i] = make_float4(0.f, 0.f, 0.f, 0.f);

    for (int t0 = 0; t0 < NKV; t0 += TKV) {
        __syncthreads();
#pragma unroll
        for (int i = 0; i < 4; i++) {
            int li = threadIdx.x + i * 256;
            int j  = li >> 3;
            int d4 = li & 7;
            size_t base = ((size_t)b * NKV + t0 + j) * 512 + hh * HD;
            sK[j * 8 + d4] = ((const float4*)&g_kv[base])[d4];
            sV[j * 8 + d4] = ((const float4*)&g_kv[base + 256])[d4];
        }
        __syncthreads();

        for (int j = 0; j < TKV; j++) {
            float s = 0.f;
#pragma unroll
            for (int d4 = 0; d4 < 8; d4++) {
                float4 kk = sK[j * 8 + d4];
                s += q4[d4].x * kk.x + q4[d4].y * kk.y + q4[d4].z * kk.z + q4[d4].w * kk.w;
            }
            s *= scale;
            float p;
            if (s <= m) {
                p = __expf(s - m);
            } else {
                float corr = __expf(m - s);
                l *= corr;
#pragma unroll
                for (int d4 = 0; d4 < 8; d4++) {
                    acc[d4].x *= corr; acc[d4].y *= corr;
                    acc[d4].z *= corr; acc[d4].w *= corr;
                }
                m = s;
                p = 1.f;
            }
            l += p;
#pragma unroll
            for (int d4 = 0; d4 < 8; d4++) {
                float4 vv = sV[j * 8 + d4];
                acc[d4].x += p * vv.x; acc[d4].y += p * vv.y;
                acc[d4].z += p * vv.z; acc[d4].w += p * vv.w;
            }
        }
    }

    float inv = 1.f / l;
    float4* op = (float4*)&g_attn[((size_t)b * NN + qi) * CC + hh * HD];
#pragma unroll
    for (int d4 = 0; d4 < 8; d4++) {
        float4 a = acc[d4];
        op[d4] = make_float4(a.x * inv, a.y * inv, a.z * inv, a.w * inv);
    }
}

// ---------------- launch ----------------
extern "C" void kernel_launch(void* const* d_in, const int* in_sizes, int n_in,
                              void* d_out, int out_size)
{
    const float* x      = (const float*)d_in[0];
    const float* q_w    = (const float*)d_in[1];
    const float* q_b    = (const float*)d_in[2];
    const float* kv_w   = (const float*)d_in[3];
    const float* kv_b   = (const float*)d_in[4];
    const float* sr_w   = (const float*)d_in[5];   // [256,256,2,2] == [256,1024] row-major
    const float* sr_b   = (const float*)d_in[6];
    const float* ln_g   = (const float*)d_in[7];
    const float* ln_b   = (const float*)d_in[8];
    const float* proj_w = (const float*)d_in[9];
    const float* proj_b = (const float*)d_in[10];
    float* out = (float*)d_out;

    float* gq  = nullptr; cudaGetSymbolAddress((void**)&gq,  g_q);
    float* gim = nullptr; cudaGetSymbolAddress((void**)&gim, g_im2col);
    float* gxs = nullptr; cudaGetSymbolAddress((void**)&gxs, g_xsr);
    float* gkv = nullptr; cudaGetSymbolAddress((void**)&gkv, g_kv);
    float* gat = nullptr; cudaGetSymbolAddress((void**)&gat, g_attn);

    // 1) Q projection: [16384,256] = x @ q_w^T + q_b
    {
        dim3 grid(CC / 64, (BB * NN) / 64);
        gemm_bt_kernel<<<grid, 256>>>(x, q_w, q_b, gq, BB * NN, CC, CC);
    }

    // 2a) im2col for the stride-2 2x2 conv
    {
        int total = BB * NKV * 1024;
        im2col_kernel<<<total / 256, 256>>>(x);
    }

    // 2b) conv as GEMM: [4096,256] = im2col[4096,1024] @ sr_w[256,1024]^T + sr_b
    {
        dim3 grid(CC / 64, (BB * NKV) / 64);
        gemm_bt_kernel<<<grid, 256>>>(gim, sr_w, sr_b, gxs, BB * NKV, CC, 1024);
    }

    // 3) LayerNorm (in place on g_xsr)
    ln_kernel<<<BB * NKV, 256>>>(ln_g, ln_b);

    // 4) KV projection: [4096,512] = x_ @ kv_w^T + kv_b
    {
        dim3 grid(512 / 64, (BB * NKV) / 64);
        gemm_bt_kernel<<<grid, 256>>>(gxs, kv_w, kv_b, gkv, BB * NKV, 512, CC);
    }

    // 5) fused attention -> g_attn [b, n, h*32+d]
    {
        dim3 grid(NN / 256, HEADS, BB);
        attn_kernel<<<grid, 256>>>();
    }

    // 6) output projection: out = attn @ proj_w^T + proj_b
    {
        dim3 grid(CC / 64, (BB * NN) / 64);
        gemm_bt_kernel<<<grid, 256>>>(gat, proj_w, proj_b, out, BB * NN, CC, CC);
    }
}

// round 3
// speedup vs baseline: 1.3292x; 1.3292x over previous
#include <cuda_runtime.h>
#include <cuda_bf16.h>
#include <math.h>
#include <cstdint>

// ---------------- constants ----------------
#define BB 4
#define NN 4096
#define CC 256
#define HEADS 8
#define HD 32
#define NKV 1024
#define EPS 1e-5f

typedef unsigned long long u64;

// ---------------- scratch (device globals) ----------------
__device__ float g_q[BB * NN * CC];          // 16 MB
__device__ float g_xsr[BB * NKV * CC];       //  4 MB
__device__ float g_kv[BB * NKV * 512];       //  8 MB
__device__ float g_attn[BB * NN * CC];       // 16 MB
__device__ float g_srw[CC * 1024];           //  1 MB  sr_w reordered [co][khw*256+ci]

// ---------------- f32x2 packed math ----------------
__device__ __forceinline__ u64 fma2(u64 a, u64 b, u64 c) {
    u64 d; asm("fma.rn.f32x2 %0, %1, %2, %3;" : "=l"(d) : "l"(a), "l"(b), "l"(c)); return d;
}
__device__ __forceinline__ u64 mul2(u64 a, u64 b) {
    u64 d; asm("mul.rn.f32x2 %0, %1, %2;" : "=l"(d) : "l"(a), "l"(b)); return d;
}
__device__ __forceinline__ u64 add2(u64 a, u64 b) {
    u64 d; asm("add.rn.f32x2 %0, %1, %2;" : "=l"(d) : "l"(a), "l"(b)); return d;
}
__device__ __forceinline__ u64 pack2(float lo, float hi) {
    u64 d; asm("mov.b64 %0, {%1, %2};" : "=l"(d) : "f"(lo), "f"(hi)); return d;
}
__device__ __forceinline__ void unpack2(float& lo, float& hi, u64 a) {
    asm("mov.b64 {%0, %1}, %2;" : "=f"(lo), "=f"(hi) : "l"(a));
}

// ---------------- tf32 warp-mma GEMM: C[M,N] = A[M,K] @ B[N,K]^T + bias ----------------
// Block tile 128x128, 8 warps, warp tile 64x32 (2x4 warp grid), K-stage 32,
// double-buffered SMEM with row stride 36 floats (conflict-free).
#define SROW 36
#define STAGE_FLOATS (128 * SROW)
#define GSM_BYTES (4 * STAGE_FLOATS * 4)   // 2 bufs * (A+B) = 73728 B

__device__ __forceinline__ uint32_t to_tf32(float v) {
    uint32_t o; asm("cvt.rna.tf32.f32 %0, %1;" : "=r"(o) : "f"(v)); return o;
}

__device__ __forceinline__ void mma_tf32(float* d, const uint32_t* a, const uint32_t* b) {
    asm volatile(
        "mma.sync.aligned.m16n8k8.row.col.f32.tf32.tf32.f32 "
        "{%0,%1,%2,%3}, {%4,%5,%6,%7}, {%8,%9}, {%0,%1,%2,%3};\n"
        : "+f"(d[0]), "+f"(d[1]), "+f"(d[2]), "+f"(d[3])
        : "r"(a[0]), "r"(a[1]), "r"(a[2]), "r"(a[3]), "r"(b[0]), "r"(b[1]));
}

template <bool GATHER>
__global__ void __launch_bounds__(256) gemm_mma(const float* __restrict__ A,
                                                const float* __restrict__ B,
                                                const float* __restrict__ bias,
                                                float* __restrict__ C,
                                                int M, int N, int K)
{
    extern __shared__ float sm[];
    float* sA = sm;                       // [2][STAGE_FLOATS]
    float* sB = sm + 2 * STAGE_FLOATS;    // [2][STAGE_FLOATS]

    const int tid = threadIdx.x;
    const int lane = tid & 31;
    const int wid = tid >> 5;
    const int wm = wid >> 2;              // 0..1
    const int wn = wid & 3;               // 0..3
    const int rowBase = blockIdx.y * 128;
    const int colBase = blockIdx.x * 128;

    const int f4 = tid & 7;               // which float4 in the 32-wide k slab
    const int r0 = tid >> 3;               // 0..31

    const int S = K >> 5;

    float4 ra[4], rb[4];

    auto issue_loads = [&](int s) {
        int k0 = s << 5;
#pragma unroll
        for (int p = 0; p < 4; p++) {
            int row = p * 32 + r0;
            const float* srcA;
            if (GATHER) {
                // conv-as-GEMM: A row gathers x; K dim is khw*256+ci
                int grow = rowBase + row;
                int khw = k0 >> 8;
                int ci0 = (k0 & 255) + f4 * 4;
                int bI = grow >> 10, t = grow & 1023;
                int ii = t >> 5, jj = t & 31;
                int y = 2 * ii + (khw >> 1), xx = 2 * jj + (khw & 1);
                srcA = A + ((size_t)((bI << 12) + y * 64 + xx)) * 256 + ci0;
            } else {
                srcA = A + (size_t)(rowBase + row) * K + k0 + f4 * 4;
            }
            ra[p] = *(const float4*)srcA;
            rb[p] = *(const float4*)(B + (size_t)(colBase + row) * K + k0 + f4 * 4);
        }
    };

    auto store_stage = [&](int buf) {
        float* dA = sA + buf * STAGE_FLOATS;
        float* dB = sB + buf * STAGE_FLOATS;
#pragma unroll
        for (int p = 0; p < 4; p++) {
            int row = p * 32 + r0;
            uint4 ca, cb;
            ca.x = to_tf32(ra[p].x); ca.y = to_tf32(ra[p].y);
            ca.z = to_tf32(ra[p].z); ca.w = to_tf32(ra[p].w);
            cb.x = to_tf32(rb[p].x); cb.y = to_tf32(rb[p].y);
            cb.z = to_tf32(rb[p].z); cb.w = to_tf32(rb[p].w);
            *(uint4*)&dA[row * SROW + f4 * 4] = ca;
            *(uint4*)&dB[row * SROW + f4 * 4] = cb;
        }
    };

    float acc[4][4][4];
#pragma unroll
    for (int i = 0; i < 4; i++)
#pragma unroll
        for (int j = 0; j < 4; j++)
#pragma unroll
            for (int q = 0; q < 4; q++) acc[i][j][q] = 0.f;

    const int row = lane >> 2;    // groupID
    const int col = lane & 3;     // threadID in group

    issue_loads(0);
    store_stage(0);
    __syncthreads();

    for (int s = 0; s < S; s++) {
        int buf = s & 1;
        if (s + 1 < S) issue_loads(s + 1);

        const float* bA = sA + buf * STAGE_FLOATS + (wm * 64) * SROW;
        const float* bB = sB + buf * STAGE_FLOATS + (wn * 32) * SROW;
#pragma unroll
        for (int ks = 0; ks < 4; ks++) {
            int kb = ks * 8;
            uint32_t a[4][4], b[4][2];
#pragma unroll
            for (int i = 0; i < 4; i++) {
                const float* pa = bA + i * 16 * SROW + kb;
                a[i][0] = __float_as_uint(pa[row * SROW + col]);
                a[i][1] = __float_as_uint(pa[(row + 8) * SROW + col]);
                a[i][2] = __float_as_uint(pa[row * SROW + col + 4]);
                a[i][3] = __float_as_uint(pa[(row + 8) * SROW + col + 4]);
            }
#pragma unroll
            for (int j = 0; j < 4; j++) {
                const float* pb = bB + j * 8 * SROW + kb;
                b[j][0] = __float_as_uint(pb[row * SROW + col]);
                b[j][1] = __float_as_uint(pb[row * SROW + col + 4]);
            }
#pragma unroll
            for (int i = 0; i < 4; i++)
#pragma unroll
                for (int j = 0; j < 4; j++)
                    mma_tf32(acc[i][j], a[i], b[j]);
        }

        if (s + 1 < S) store_stage(buf ^ 1);
        __syncthreads();
    }

    // epilogue: bias + store
#pragma unroll
    for (int i = 0; i < 4; i++) {
#pragma unroll
        for (int j = 0; j < 4; j++) {
            int r = rowBase + wm * 64 + i * 16 + row;
            int c = colBase + wn * 32 + j * 8 + col * 2;
            float b0 = bias[c], b1 = bias[c + 1];
            float2 o0 = make_float2(acc[i][j][0] + b0, acc[i][j][1] + b1);
            float2 o1 = make_float2(acc[i][j][2] + b0, acc[i][j][3] + b1);
            *(float2*)&C[(size_t)r * N + c] = o0;
            *(float2*)&C[(size_t)(r + 8) * N + c] = o1;
        }
    }
}

// ---------------- sr_w reorder: [co][ci][kh][kw] -> [co][khw*256+ci] ----------------
__global__ void wtr_kernel(const float* __restrict__ sr_w)
{
    int idx = blockIdx.x * blockDim.x + threadIdx.x;
    int co = idx >> 10;
    int khw = (idx >> 8) & 3;
    int ci = idx & 255;
    g_srw[idx] = sr_w[co * 1024 + ci * 4 + khw];
}

// ---------------- LayerNorm over C=256 ----------------
__global__ void ln_kernel(const float* __restrict__ g, const float* __restrict__ bta)
{
    __shared__ float sbuf[256];
    int t = blockIdx.x;
    int c = threadIdx.x;
    float v = g_xsr[(size_t)t * CC + c];
    sbuf[c] = v;
    __syncthreads();
    for (int s = 128; s > 0; s >>= 1) {
        if (c < s) sbuf[c] += sbuf[c + s];
        __syncthreads();
    }
    float mu = sbuf[0] * (1.f / CC);
    __syncthreads();
    float d = v - mu;
    sbuf[c] = d * d;
    __syncthreads();
    for (int s = 128; s > 0; s >>= 1) {
        if (c < s) sbuf[c] += sbuf[c + s];
        __syncthreads();
    }
    float var = sbuf[0] * (1.f / CC);
    float r = rsqrtf(var + EPS);
    g_xsr[(size_t)t * CC + c] = d * r * g[c] + bta[c];
}

// ---------------- fused attention, f32x2 packed FMA ----------------
#define TKV 128
__global__ void __launch_bounds__(256) attn_kernel()
{
    __shared__ u64 sK[TKV * 16];
    __shared__ u64 sV[TKV * 16];

    const float scale = 0.17677669529663687f;
    int b = blockIdx.z;
    int hh = blockIdx.y;
    int qi = blockIdx.x * 256 + threadIdx.x;

    u64 q2[16];
    {
        const ulonglong2* qp = (const ulonglong2*)&g_q[((size_t)b * NN + qi) * CC + hh * HD];
        u64 sc2 = pack2(scale, scale);
#pragma unroll
        for (int i = 0; i < 8; i++) {
            ulonglong2 t = qp[i];
            q2[2 * i] = mul2(t.x, sc2);
            q2[2 * i + 1] = mul2(t.y, sc2);
        }
    }

    float m = -1e30f, l = 0.f;
    u64 o2[16];
#pragma unroll
    for (int i = 0; i < 16; i++) o2[i] = 0ULL;

    for (int t0 = 0; t0 < NKV; t0 += TKV) {
        __syncthreads();
#pragma unroll
        for (int i = 0; i < 4; i++) {
            int li = threadIdx.x + i * 256;
            int j = li >> 3;
            int d4 = li & 7;
            size_t base = ((size_t)b * NKV + t0 + j) * 512 + hh * HD;
            ((float4*)sK)[j * 8 + d4] = ((const float4*)&g_kv[base])[d4];
            ((float4*)sV)[j * 8 + d4] = ((const float4*)&g_kv[base + 256])[d4];
        }
        __syncthreads();

        for (int j = 0; j < TKV; j++) {
            const ulonglong2* kp = (const ulonglong2*)&sK[j * 16];
            u64 a0 = 0ULL, a1 = 0ULL, a2 = 0ULL, a3 = 0ULL;
#pragma unroll
            for (int dd = 0; dd < 4; dd++) {
                ulonglong2 k01 = kp[dd * 2];
                ulonglong2 k23 = kp[dd * 2 + 1];
                a0 = fma2(q2[dd * 4 + 0], k01.x, a0);
                a1 = fma2(q2[dd * 4 + 1], k01.y, a1);
                a2 = fma2(q2[dd * 4 + 2], k23.x, a2);
                a3 = fma2(q2[dd * 4 + 3], k23.y, a3);
            }
            a0 = add2(a0, a1);
            a2 = add2(a2, a3);
            a0 = add2(a0, a2);
            float lo, hi;
            unpack2(lo, hi, a0);
            float s = lo + hi;

            float p;
            if (s <= m) {
                p = __expf(s - m);
            } else {
                float corr = __expf(m - s);
                l *= corr;
                u64 c2 = pack2(corr, corr);
#pragma unroll
                for (int d = 0; d < 16; d++) o2[d] = mul2(o2[d], c2);
                m = s;
                p = 1.f;
            }
            l += p;

            u64 p2 = pack2(p, p);
            const ulonglong2* vp = (const ulonglong2*)&sV[j * 16];
#pragma unroll
            for (int dd = 0; dd < 8; dd++) {
                ulonglong2 vv = vp[dd];
                o2[2 * dd] = fma2(p2, vv.x, o2[2 * dd]);
                o2[2 * dd + 1] = fma2(p2, vv.y, o2[2 * dd + 1]);
            }
        }
    }

    float inv = 1.f / l;
    u64 inv2 = pack2(inv, inv);
    ulonglong2* op = (ulonglong2*)&g_attn[((size_t)b * NN + qi) * CC + hh * HD];
#pragma unroll
    for (int dd = 0; dd < 8; dd++) {
        ulonglong2 o;
        o.x = mul2(o2[2 * dd], inv2);
        o.y = mul2(o2[2 * dd + 1], inv2);
        op[dd] = o;
    }
}

// ---------------- launch ----------------
extern "C" void kernel_launch(void* const* d_in, const int* in_sizes, int n_in,
                              void* d_out, int out_size)
{
    const float* x      = (const float*)d_in[0];
    const float* q_w    = (const float*)d_in[1];
    const float* q_b    = (const float*)d_in[2];
    const float* kv_w   = (const float*)d_in[3];
    const float* kv_b   = (const float*)d_in[4];
    const float* sr_w   = (const float*)d_in[5];
    const float* sr_b   = (const float*)d_in[6];
    const float* ln_g   = (const float*)d_in[7];
    const float* ln_b   = (const float*)d_in[8];
    const float* proj_w = (const float*)d_in[9];
    const float* proj_b = (const float*)d_in[10];
    float* out = (float*)d_out;

    float* gq  = nullptr; cudaGetSymbolAddress((void**)&gq,  g_q);
    float* gxs = nullptr; cudaGetSymbolAddress((void**)&gxs, g_xsr);
    float* gkv = nullptr; cudaGetSymbolAddress((void**)&gkv, g_kv);
    float* gat = nullptr; cudaGetSymbolAddress((void**)&gat, g_attn);
    float* gsw = nullptr; cudaGetSymbolAddress((void**)&gsw, g_srw);

    cudaFuncSetAttribute(gemm_mma<false>, cudaFuncAttributeMaxDynamicSharedMemorySize, GSM_BYTES);
    cudaFuncSetAttribute(gemm_mma<true>,  cudaFuncAttributeMaxDynamicSharedMemorySize, GSM_BYTES);

    // 0) reorder sr_w
    wtr_kernel<<<(CC * 1024) / 256, 256>>>(sr_w);

    // 1) Q projection: [16384,256] = x @ q_w^T + q_b
    gemm_mma<false><<<dim3(2, 128), 256, GSM_BYTES>>>(x, q_w, q_b, gq, BB * NN, CC, CC);

    // 2) conv as gathered GEMM: [4096,256] = gather(x)[4096,1024] @ g_srw^T + sr_b
    gemm_mma<true><<<dim3(2, 32), 256, GSM_BYTES>>>(x, gsw, sr_b, gxs, BB * NKV, CC, 1024);

    // 3) LayerNorm in place
    ln_kernel<<<BB * NKV, 256>>>(ln_g, ln_b);

    // 4) KV projection: [4096,512]
    gemm_mma<false><<<dim3(4, 32), 256, GSM_BYTES>>>(gxs, kv_w, kv_b, gkv, BB * NKV, 512, CC);

    // 5) fused attention
    attn_kernel<<<dim3(NN / 256, HEADS, BB), 256>>>();

    // 6) output projection
    gemm_mma<false><<<dim3(2, 128), 256, GSM_BYTES>>>(gat, proj_w, proj_b, out, BB * NN, CC, CC);
}

// round 4
// speedup vs baseline: 4.3396x; 3.2648x over previous
#include <cuda_runtime.h>
#include <cuda_fp16.h>
#include <cuda_bf16.h>
#include <math.h>
#include <cstdint>

// ---------------- constants ----------------
#define BB 4
#define NN 4096
#define CC 256
#define HEADS 8
#define HD 32
#define NKV 1024
#define EPS 1e-5f

// ---------------- scratch (device globals) ----------------
__device__ float g_q[BB * NN * CC];          // 16 MB
__device__ float g_xsr[BB * NKV * CC];       //  4 MB
__device__ float g_kv[BB * NKV * 512];       //  8 MB
__device__ float g_attn[BB * NN * CC];       // 16 MB
__device__ float g_srw[CC * 1024];           //  1 MB  sr_w reordered [co][khw*256+ci]

// ---------------- tf32 warp-mma GEMM: C[M,N] = A[M,K] @ B[N,K]^T + bias ----------------
#define SROW 36
#define STAGE_FLOATS (128 * SROW)
#define GSM_BYTES (4 * STAGE_FLOATS * 4)   // 73728 B

__device__ __forceinline__ uint32_t to_tf32(float v) {
    uint32_t o; asm("cvt.rna.tf32.f32 %0, %1;" : "=r"(o) : "f"(v)); return o;
}

__device__ __forceinline__ void mma_tf32(float* d, const uint32_t* a, const uint32_t* b) {
    asm volatile(
        "mma.sync.aligned.m16n8k8.row.col.f32.tf32.tf32.f32 "
        "{%0,%1,%2,%3}, {%4,%5,%6,%7}, {%8,%9}, {%0,%1,%2,%3};\n"
        : "+f"(d[0]), "+f"(d[1]), "+f"(d[2]), "+f"(d[3])
        : "r"(a[0]), "r"(a[1]), "r"(a[2]), "r"(a[3]), "r"(b[0]), "r"(b[1]));
}

template <bool GATHER>
__global__ void __launch_bounds__(256) gemm_mma(const float* __restrict__ A,
                                                const float* __restrict__ B,
                                                const float* __restrict__ bias,
                                                float* __restrict__ C,
                                                int M, int N, int K)
{
    extern __shared__ float sm[];
    float* sA = sm;
    float* sB = sm + 2 * STAGE_FLOATS;

    const int tid = threadIdx.x;
    const int lane = tid & 31;
    const int wid = tid >> 5;
    const int wm = wid >> 2;
    const int wn = wid & 3;
    const int rowBase = blockIdx.y * 128;
    const int colBase = blockIdx.x * 128;

    const int f4 = tid & 7;
    const int r0 = tid >> 3;

    const int S = K >> 5;

    float4 ra[4], rb[4];

    auto issue_loads = [&](int s) {
        int k0 = s << 5;
#pragma unroll
        for (int p = 0; p < 4; p++) {
            int row = p * 32 + r0;
            const float* srcA;
            if (GATHER) {
                int grow = rowBase + row;
                int khw = k0 >> 8;
                int ci0 = (k0 & 255) + f4 * 4;
                int bI = grow >> 10, t = grow & 1023;
                int ii = t >> 5, jj = t & 31;
                int y = 2 * ii + (khw >> 1), xx = 2 * jj + (khw & 1);
                srcA = A + ((size_t)((bI << 12) + y * 64 + xx)) * 256 + ci0;
            } else {
                srcA = A + (size_t)(rowBase + row) * K + k0 + f4 * 4;
            }
            ra[p] = *(const float4*)srcA;
            rb[p] = *(const float4*)(B + (size_t)(colBase + row) * K + k0 + f4 * 4);
        }
    };

    auto store_stage = [&](int buf) {
        float* dA = sA + buf * STAGE_FLOATS;
        float* dB = sB + buf * STAGE_FLOATS;
#pragma unroll
        for (int p = 0; p < 4; p++) {
            int row = p * 32 + r0;
            uint4 ca, cb;
            ca.x = to_tf32(ra[p].x); ca.y = to_tf32(ra[p].y);
            ca.z = to_tf32(ra[p].z); ca.w = to_tf32(ra[p].w);
            cb.x = to_tf32(rb[p].x); cb.y = to_tf32(rb[p].y);
            cb.z = to_tf32(rb[p].z); cb.w = to_tf32(rb[p].w);
            *(uint4*)&dA[row * SROW + f4 * 4] = ca;
            *(uint4*)&dB[row * SROW + f4 * 4] = cb;
        }
    };

    float acc[4][4][4];
#pragma unroll
    for (int i = 0; i < 4; i++)
#pragma unroll
        for (int j = 0; j < 4; j++)
#pragma unroll
            for (int q = 0; q < 4; q++) acc[i][j][q] = 0.f;

    const int row = lane >> 2;
    const int col = lane & 3;

    issue_loads(0);
    store_stage(0);
    __syncthreads();

    for (int s = 0; s < S; s++) {
        int buf = s & 1;
        if (s + 1 < S) issue_loads(s + 1);

        const float* bA = sA + buf * STAGE_FLOATS + (wm * 64) * SROW;
        const float* bB = sB + buf * STAGE_FLOATS + (wn * 32) * SROW;
#pragma unroll
        for (int ks = 0; ks < 4; ks++) {
            int kb = ks * 8;
            uint32_t a[4][4], b[4][2];
#pragma unroll
            for (int i = 0; i < 4; i++) {
                const float* pa = bA + i * 16 * SROW + kb;
                a[i][0] = __float_as_uint(pa[row * SROW + col]);
                a[i][1] = __float_as_uint(pa[(row + 8) * SROW + col]);
                a[i][2] = __float_as_uint(pa[row * SROW + col + 4]);
                a[i][3] = __float_as_uint(pa[(row + 8) * SROW + col + 4]);
            }
#pragma unroll
            for (int j = 0; j < 4; j++) {
                const float* pb = bB + j * 8 * SROW + kb;
                b[j][0] = __float_as_uint(pb[row * SROW + col]);
                b[j][1] = __float_as_uint(pb[row * SROW + col + 4]);
            }
#pragma unroll
            for (int i = 0; i < 4; i++)
#pragma unroll
                for (int j = 0; j < 4; j++)
                    mma_tf32(acc[i][j], a[i], b[j]);
        }

        if (s + 1 < S) store_stage(buf ^ 1);
        __syncthreads();
    }

#pragma unroll
    for (int i = 0; i < 4; i++) {
#pragma unroll
        for (int j = 0; j < 4; j++) {
            int r = rowBase + wm * 64 + i * 16 + row;
            int c = colBase + wn * 32 + j * 8 + col * 2;
            float b0 = bias[c], b1 = bias[c + 1];
            float2 o0 = make_float2(acc[i][j][0] + b0, acc[i][j][1] + b1);
            float2 o1 = make_float2(acc[i][j][2] + b0, acc[i][j][3] + b1);
            *(float2*)&C[(size_t)r * N + c] = o0;
            *(float2*)&C[(size_t)(r + 8) * N + c] = o1;
        }
    }
}

// ---------------- sr_w reorder ----------------
__global__ void wtr_kernel(const float* __restrict__ sr_w)
{
    int idx = blockIdx.x * blockDim.x + threadIdx.x;
    int co = idx >> 10;
    int khw = (idx >> 8) & 3;
    int ci = idx & 255;
    g_srw[idx] = sr_w[co * 1024 + ci * 4 + khw];
}

// ---------------- LayerNorm over C=256 ----------------
__global__ void ln_kernel(const float* __restrict__ g, const float* __restrict__ bta)
{
    __shared__ float sbuf[256];
    int t = blockIdx.x;
    int c = threadIdx.x;
    float v = g_xsr[(size_t)t * CC + c];
    sbuf[c] = v;
    __syncthreads();
    for (int s = 128; s > 0; s >>= 1) {
        if (c < s) sbuf[c] += sbuf[c + s];
        __syncthreads();
    }
    float mu = sbuf[0] * (1.f / CC);
    __syncthreads();
    float d = v - mu;
    sbuf[c] = d * d;
    __syncthreads();
    for (int s = 128; s > 0; s >>= 1) {
        if (c < s) sbuf[c] += sbuf[c + s];
        __syncthreads();
    }
    float var = sbuf[0] * (1.f / CC);
    float r = rsqrtf(var + EPS);
    g_xsr[(size_t)t * CC + c] = d * r * g[c] + bta[c];
}

// ---------------- fp16 tensor-core flash attention ----------------
#define TKV 64
#define KPAD 40     // K row stride in halves
#define VPAD 72     // Vt row stride in halves

__device__ __forceinline__ float ex2f(float x) {
    float r; asm("ex2.approx.f32 %0, %1;" : "=f"(r) : "f"(x)); return r;
}
__device__ __forceinline__ void mma_f16(float* d, const uint32_t* a, const uint32_t* b) {
    asm volatile(
        "mma.sync.aligned.m16n8k16.row.col.f32.f16.f16.f32 "
        "{%0,%1,%2,%3}, {%4,%5,%6,%7}, {%8,%9}, {%0,%1,%2,%3};\n"
        : "+f"(d[0]), "+f"(d[1]), "+f"(d[2]), "+f"(d[3])
        : "r"(a[0]), "r"(a[1]), "r"(a[2]), "r"(a[3]), "r"(b[0]), "r"(b[1]));
}

__global__ void __launch_bounds__(256) attn_fa()
{
    __shared__ __half sK[TKV * KPAD];     // [kv][hd]
    __shared__ __half sVt[HD * VPAD];     // [hd][kv]

    const int tid = threadIdx.x;
    const int lane = tid & 31;
    const int wid = tid >> 5;
    const int g = lane >> 2;
    const int t4 = lane & 3;

    const int b = blockIdx.z;
    const int h = blockIdx.y;
    const int q0 = blockIdx.x * 128 + wid * 16;

    const float qscale = 0.17677669529663687f * 1.4426950408889634f;

    uint32_t aq[2][4];
    {
        const float* qr0 = g_q + ((size_t)(b * NN + q0 + g)) * CC + h * HD;
        const float* qr8 = qr0 + 8 * CC;
#pragma unroll
        for (int ks = 0; ks < 2; ks++) {
            int c0 = ks * 16 + 2 * t4;
            float2 a0 = *(const float2*)(qr0 + c0);
            float2 a1 = *(const float2*)(qr8 + c0);
            float2 a2 = *(const float2*)(qr0 + c0 + 8);
            float2 a3 = *(const float2*)(qr8 + c0 + 8);
            __half2 h0 = __floats2half2_rn(a0.x * qscale, a0.y * qscale);
            __half2 h1 = __floats2half2_rn(a1.x * qscale, a1.y * qscale);
            __half2 h2 = __floats2half2_rn(a2.x * qscale, a2.y * qscale);
            __half2 h3 = __floats2half2_rn(a3.x * qscale, a3.y * qscale);
            aq[ks][0] = *(uint32_t*)&h0;
            aq[ks][1] = *(uint32_t*)&h1;
            aq[ks][2] = *(uint32_t*)&h2;
            aq[ks][3] = *(uint32_t*)&h3;
        }
    }

    float m[2] = {-1e30f, -1e30f};
    float l[2] = {0.f, 0.f};
    float o[4][4];
#pragma unroll
    for (int i = 0; i < 4; i++)
#pragma unroll
        for (int j = 0; j < 4; j++) o[i][j] = 0.f;

    const int lrow = tid >> 2;           // kv row 0..63
    const int lcb = (tid & 3) * 8;       // hd col base

    for (int t0 = 0; t0 < NKV; t0 += TKV) {
        {
            const float* src = g_kv + ((size_t)(b * NKV + t0 + lrow)) * 512 + h * HD + lcb;
            float4 k0 = *(const float4*)(src);
            float4 k1 = *(const float4*)(src + 4);
            __half2* kd = (__half2*)&sK[lrow * KPAD + lcb];
            kd[0] = __floats2half2_rn(k0.x, k0.y);
            kd[1] = __floats2half2_rn(k0.z, k0.w);
            kd[2] = __floats2half2_rn(k1.x, k1.y);
            kd[3] = __floats2half2_rn(k1.z, k1.w);
            float4 v0 = *(const float4*)(src + 256);
            float4 v1 = *(const float4*)(src + 260);
            sVt[(lcb + 0) * VPAD + lrow] = __float2half_rn(v0.x);
            sVt[(lcb + 1) * VPAD + lrow] = __float2half_rn(v0.y);
            sVt[(lcb + 2) * VPAD + lrow] = __float2half_rn(v0.z);
            sVt[(lcb + 3) * VPAD + lrow] = __float2half_rn(v0.w);
            sVt[(lcb + 4) * VPAD + lrow] = __float2half_rn(v1.x);
            sVt[(lcb + 5) * VPAD + lrow] = __float2half_rn(v1.y);
            sVt[(lcb + 6) * VPAD + lrow] = __float2half_rn(v1.z);
            sVt[(lcb + 7) * VPAD + lrow] = __float2half_rn(v1.w);
        }
        __syncthreads();

        float c[8][4];
#pragma unroll
        for (int nt = 0; nt < 8; nt++) {
            c[nt][0] = 0.f; c[nt][1] = 0.f; c[nt][2] = 0.f; c[nt][3] = 0.f;
            int krow = nt * 8 + g;
#pragma unroll
            for (int ks = 0; ks < 2; ks++) {
                uint32_t bfr[2];
                const __half* kp = &sK[krow * KPAD + ks * 16 + 2 * t4];
                bfr[0] = *(const uint32_t*)kp;
                bfr[1] = *(const uint32_t*)(kp + 8);
                mma_f16(c[nt], aq[ks], bfr);
            }
        }

#pragma unroll
        for (int rh = 0; rh < 2; rh++) {
            float mx = c[0][2 * rh];
#pragma unroll
            for (int nt = 0; nt < 8; nt++)
                mx = fmaxf(mx, fmaxf(c[nt][2 * rh], c[nt][2 * rh + 1]));
            mx = fmaxf(mx, __shfl_xor_sync(0xFFFFFFFF, mx, 1));
            mx = fmaxf(mx, __shfl_xor_sync(0xFFFFFFFF, mx, 2));
            float mnew = fmaxf(m[rh], mx);
            float alpha = ex2f(m[rh] - mnew);
#pragma unroll
            for (int i = 0; i < 4; i++) {
                o[i][2 * rh] *= alpha;
                o[i][2 * rh + 1] *= alpha;
            }
            float sum = 0.f;
#pragma unroll
            for (int nt = 0; nt < 8; nt++) {
                float p0 = ex2f(c[nt][2 * rh] - mnew);
                float p1 = ex2f(c[nt][2 * rh + 1] - mnew);
                c[nt][2 * rh] = p0;
                c[nt][2 * rh + 1] = p1;
                sum += p0 + p1;
            }
            sum += __shfl_xor_sync(0xFFFFFFFF, sum, 1);
            sum += __shfl_xor_sync(0xFFFFFFFF, sum, 2);
            l[rh] = l[rh] * alpha + sum;
            m[rh] = mnew;
        }

        uint32_t ap[4][4];
#pragma unroll
        for (int k = 0; k < 4; k++) {
            __half2 p0 = __floats2half2_rn(c[2 * k][0], c[2 * k][1]);
            __half2 p1 = __floats2half2_rn(c[2 * k][2], c[2 * k][3]);
            __half2 p2 = __floats2half2_rn(c[2 * k + 1][0], c[2 * k + 1][1]);
            __half2 p3 = __floats2half2_rn(c[2 * k + 1][2], c[2 * k + 1][3]);
            ap[k][0] = *(uint32_t*)&p0;
            ap[k][1] = *(uint32_t*)&p1;
            ap[k][2] = *(uint32_t*)&p2;
            ap[k][3] = *(uint32_t*)&p3;
        }

#pragma unroll
        for (int nt = 0; nt < 4; nt++) {
            int vrow = nt * 8 + g;
#pragma unroll
            for (int k = 0; k < 4; k++) {
                uint32_t bfr[2];
                const __half* vp = &sVt[vrow * VPAD + k * 16 + 2 * t4];
                bfr[0] = *(const uint32_t*)vp;
                bfr[1] = *(const uint32_t*)(vp + 8);
                mma_f16(o[nt], ap[k], bfr);
            }
        }
        __syncthreads();
    }

    float inv0 = 1.f / l[0];
    float inv1 = 1.f / l[1];
    float* out0 = g_attn + ((size_t)(b * NN + q0 + g)) * CC + h * HD;
    float* out8 = out0 + 8 * CC;
#pragma unroll
    for (int nt = 0; nt < 4; nt++) {
        int cidx = nt * 8 + 2 * t4;
        *(float2*)(out0 + cidx) = make_float2(o[nt][0] * inv0, o[nt][1] * inv0);
        *(float2*)(out8 + cidx) = make_float2(o[nt][2] * inv1, o[nt][3] * inv1);
    }
}

// ---------------- launch ----------------
extern "C" void kernel_launch(void* const* d_in, const int* in_sizes, int n_in,
                              void* d_out, int out_size)
{
    const float* x      = (const float*)d_in[0];
    const float* q_w    = (const float*)d_in[1];
    const float* q_b    = (const float*)d_in[2];
    const float* kv_w   = (const float*)d_in[3];
    const float* kv_b   = (const float*)d_in[4];
    const float* sr_w   = (const float*)d_in[5];
    const float* sr_b   = (const float*)d_in[6];
    const float* ln_g   = (const float*)d_in[7];
    const float* ln_b   = (const float*)d_in[8];
    const float* proj_w = (const float*)d_in[9];
    const float* proj_b = (const float*)d_in[10];
    float* out = (float*)d_out;

    float* gq  = nullptr; cudaGetSymbolAddress((void**)&gq,  g_q);
    float* gxs = nullptr; cudaGetSymbolAddress((void**)&gxs, g_xsr);
    float* gkv = nullptr; cudaGetSymbolAddress((void**)&gkv, g_kv);
    float* gat = nullptr; cudaGetSymbolAddress((void**)&gat, g_attn);
    float* gsw = nullptr; cudaGetSymbolAddress((void**)&gsw, g_srw);

    cudaFuncSetAttribute(gemm_mma<false>, cudaFuncAttributeMaxDynamicSharedMemorySize, GSM_BYTES);
    cudaFuncSetAttribute(gemm_mma<true>,  cudaFuncAttributeMaxDynamicSharedMemorySize, GSM_BYTES);

    wtr_kernel<<<(CC * 1024) / 256, 256>>>(sr_w);
    gemm_mma<false><<<dim3(2, 128), 256, GSM_BYTES>>>(x, q_w, q_b, gq, BB * NN, CC, CC);
    gemm_mma<true><<<dim3(2, 32), 256, GSM_BYTES>>>(x, gsw, sr_b, gxs, BB * NKV, CC, 1024);
    ln_kernel<<<BB * NKV, 256>>>(ln_g, ln_b);
    gemm_mma<false><<<dim3(4, 32), 256, GSM_BYTES>>>(gxs, kv_w, kv_b, gkv, BB * NKV, 512, CC);
    attn_fa<<<dim3(NN / 128, HEADS, BB), 256>>>();
    gemm_mma<false><<<dim3(2, 128), 256, GSM_BYTES>>>(gat, proj_w, proj_b, out, BB * NN, CC, CC);
}

// round 5
// speedup vs baseline: 5.5451x; 1.2778x over previous
#include <cuda_runtime.h>
#include <cuda_fp16.h>
#include <math.h>
#include <cstdint>

// ---------------- constants ----------------
#define BB 4
#define NN 4096
#define CC 256
#define HEADS 8
#define HD 32
#define NKV 1024
#define EPS 1e-5f

#define QW_OFF 0
#define KV_OFF 65536
#define SRW_OFF 196608
#define PJ_OFF 458752
#define W16_TOTAL 524288

// ---------------- scratch (device globals) ----------------
__device__ __half g_q16[BB * NN * CC];       //  8 MB (pre-scaled by scale*log2e)
__device__ float  g_xsr[BB * NKV * CC];      //  4 MB
__device__ __half g_kv16[BB * NKV * 512];    //  4 MB
__device__ __half g_at16[BB * NN * CC];      //  8 MB
__device__ __half g_w16[W16_TOTAL];          //  1 MB  all weights fp16

// ---------------- PTX helpers ----------------
__device__ __forceinline__ uint32_t smem_u32(const void* p) {
    uint32_t a;
    asm("{ .reg .u64 t; cvta.to.shared.u64 t, %1; cvt.u32.u64 %0, t; }" : "=r"(a) : "l"(p));
    return a;
}
__device__ __forceinline__ void ldsm4(uint32_t* r, uint32_t addr) {
    asm volatile("ldmatrix.sync.aligned.m8n8.x4.shared.b16 {%0,%1,%2,%3}, [%4];"
        : "=r"(r[0]), "=r"(r[1]), "=r"(r[2]), "=r"(r[3]) : "r"(addr));
}
__device__ __forceinline__ void ldsm4t(uint32_t* r, uint32_t addr) {
    asm volatile("ldmatrix.sync.aligned.m8n8.x4.trans.shared.b16 {%0,%1,%2,%3}, [%4];"
        : "=r"(r[0]), "=r"(r[1]), "=r"(r[2]), "=r"(r[3]) : "r"(addr));
}
__device__ __forceinline__ void mma_f16(float* d, const uint32_t* a, const uint32_t* b) {
    asm volatile(
        "mma.sync.aligned.m16n8k16.row.col.f32.f16.f16.f32 "
        "{%0,%1,%2,%3}, {%4,%5,%6,%7}, {%8,%9}, {%0,%1,%2,%3};\n"
        : "+f"(d[0]), "+f"(d[1]), "+f"(d[2]), "+f"(d[3])
        : "r"(a[0]), "r"(a[1]), "r"(a[2]), "r"(a[3]), "r"(b[0]), "r"(b[1]));
}
__device__ __forceinline__ float ex2f(float x) {
    float r; asm("ex2.approx.f32 %0, %1;" : "=f"(r) : "f"(x)); return r;
}

// ---------------- weight prep: fp32 -> fp16, sr_w reordered ----------------
__global__ void prep_w(const float* __restrict__ qw, const float* __restrict__ kvw,
                       const float* __restrict__ srw, const float* __restrict__ pjw)
{
    int idx = blockIdx.x * blockDim.x + threadIdx.x;
    float v;
    if (idx < KV_OFF) {
        v = qw[idx];
    } else if (idx < SRW_OFF) {
        v = kvw[idx - KV_OFF];
    } else if (idx < PJ_OFF) {
        int r = idx - SRW_OFF;
        int co = r >> 10;
        int khw = (r >> 8) & 3;
        int ci = r & 255;
        v = srw[co * 1024 + ci * 4 + khw];
    } else {
        v = pjw[idx - PJ_OFF];
    }
    g_w16[idx] = __float2half_rn(v);
}

// ---------------- fp16 warp-mma GEMM: C[M,N] = A[M,K] @ B[N,K]^T + bias, *oscale ----------------
// Block 128x128, 8 warps (2x4), warp 64x32, K-stage 32, double-buffered half smem, KP=40.
#define KP 40

template <bool A_HALF, bool GATHER, bool OUT_HALF>
__global__ void __launch_bounds__(256) gemm_h(const void* __restrict__ Av,
                                              const __half* __restrict__ B,
                                              const float* __restrict__ bias,
                                              void* __restrict__ Cv,
                                              int M, int N, int K, float oscale)
{
    __shared__ __half sA[2][128 * KP];
    __shared__ __half sB[2][128 * KP];

    const int tid = threadIdx.x;
    const int lane = tid & 31;
    const int wid = tid >> 5;
    const int wm = wid >> 2;
    const int wn = wid & 3;
    const int rowBase = blockIdx.y * 128;
    const int colBase = blockIdx.x * 128;
    const int g = lane >> 2;
    const int t4 = lane & 3;

    const int r = tid >> 1;          // 0..127 row of stage
    const int p = tid & 1;           // which 16-half chunk

    const int S = K >> 5;

    float4 raf[4];
    uint4 rah[2];
    uint4 rbh[2];

    auto issue_loads = [&](int s) {
        int k0 = s << 5;
        if (A_HALF) {
            const __half* Ah = (const __half*)Av;
            const uint4* src = (const uint4*)(Ah + (size_t)(rowBase + r) * K + k0 + p * 16);
            rah[0] = src[0]; rah[1] = src[1];
        } else {
            const float* Af;
            if (GATHER) {
                int grow = rowBase + r;
                int khw = k0 >> 8;
                int ci0 = (k0 & 255) + p * 16;
                int bI = grow >> 10, tt = grow & 1023;
                int ii = tt >> 5, jj = tt & 31;
                int y = 2 * ii + (khw >> 1), xx = 2 * jj + (khw & 1);
                Af = (const float*)Av + ((size_t)((bI << 12) + y * 64 + xx)) * 256 + ci0;
            } else {
                Af = (const float*)Av + (size_t)(rowBase + r) * K + k0 + p * 16;
            }
            raf[0] = ((const float4*)Af)[0];
            raf[1] = ((const float4*)Af)[1];
            raf[2] = ((const float4*)Af)[2];
            raf[3] = ((const float4*)Af)[3];
        }
        const uint4* bs = (const uint4*)(B + (size_t)(colBase + r) * K + k0 + p * 16);
        rbh[0] = bs[0]; rbh[1] = bs[1];
    };

    auto store_stage = [&](int buf) {
        __half* dA = &sA[buf][r * KP + p * 16];
        if (A_HALF) {
            ((uint4*)dA)[0] = rah[0];
            ((uint4*)dA)[1] = rah[1];
        } else {
            __half2* d2 = (__half2*)dA;
            d2[0] = __floats2half2_rn(raf[0].x, raf[0].y);
            d2[1] = __floats2half2_rn(raf[0].z, raf[0].w);
            d2[2] = __floats2half2_rn(raf[1].x, raf[1].y);
            d2[3] = __floats2half2_rn(raf[1].z, raf[1].w);
            d2[4] = __floats2half2_rn(raf[2].x, raf[2].y);
            d2[5] = __floats2half2_rn(raf[2].z, raf[2].w);
            d2[6] = __floats2half2_rn(raf[3].x, raf[3].y);
            d2[7] = __floats2half2_rn(raf[3].z, raf[3].w);
        }
        __half* dB = &sB[buf][r * KP + p * 16];
        ((uint4*)dB)[0] = rbh[0];
        ((uint4*)dB)[1] = rbh[1];
    };

    float acc[4][4][4];
#pragma unroll
    for (int i = 0; i < 4; i++)
#pragma unroll
        for (int j = 0; j < 4; j++)
#pragma unroll
            for (int q = 0; q < 4; q++) acc[i][j][q] = 0.f;

    const uint32_t sAu = smem_u32(sA);
    const uint32_t sBu = smem_u32(sB);
    // per-thread ldmatrix row offsets (in halves)
    const uint32_t aRow = (uint32_t)((wm * 64 + (lane & 15)) * KP + (lane >> 4) * 8);
    const uint32_t bRow = (uint32_t)((wn * 32 + (lane & 7) + (lane >> 4) * 8) * KP + ((lane >> 3) & 1) * 8);

    issue_loads(0);
    store_stage(0);
    __syncthreads();

    for (int s = 0; s < S; s++) {
        int buf = s & 1;
        if (s + 1 < S) issue_loads(s + 1);

        const uint32_t baseA = sAu + buf * (128 * KP * 2);
        const uint32_t baseB = sBu + buf * (128 * KP * 2);
#pragma unroll
        for (int ks = 0; ks < 2; ks++) {
            uint32_t a[4][4];
#pragma unroll
            for (int i = 0; i < 4; i++)
                ldsm4(a[i], baseA + (aRow + i * 16 * KP + ks * 16) * 2);
#pragma unroll
            for (int j = 0; j < 2; j++) {
                uint32_t bf[4];
                ldsm4(bf, baseB + (bRow + j * 16 * KP + ks * 16) * 2);
#pragma unroll
                for (int i = 0; i < 4; i++) {
                    mma_f16(acc[i][2 * j], a[i], bf);
                    mma_f16(acc[i][2 * j + 1], a[i], bf + 2);
                }
            }
        }

        if (s + 1 < S) store_stage(buf ^ 1);
        __syncthreads();
    }

#pragma unroll
    for (int i = 0; i < 4; i++) {
#pragma unroll
        for (int jt = 0; jt < 4; jt++) {
            int rr = rowBase + wm * 64 + i * 16 + g;
            int cc = colBase + wn * 32 + jt * 8 + t4 * 2;
            float b0 = bias[cc], b1 = bias[cc + 1];
            float v00 = (acc[i][jt][0] + b0) * oscale;
            float v01 = (acc[i][jt][1] + b1) * oscale;
            float v10 = (acc[i][jt][2] + b0) * oscale;
            float v11 = (acc[i][jt][3] + b1) * oscale;
            if (OUT_HALF) {
                __half* C = (__half*)Cv;
                __half2 h0 = __floats2half2_rn(v00, v01);
                __half2 h1 = __floats2half2_rn(v10, v11);
                *(uint32_t*)&C[(size_t)rr * N + cc] = *(uint32_t*)&h0;
                *(uint32_t*)&C[(size_t)(rr + 8) * N + cc] = *(uint32_t*)&h1;
            } else {
                float* C = (float*)Cv;
                *(float2*)&C[(size_t)rr * N + cc] = make_float2(v00, v01);
                *(float2*)&C[(size_t)(rr + 8) * N + cc] = make_float2(v10, v11);
            }
        }
    }
}

// ---------------- LayerNorm: warp per token ----------------
__global__ void ln_kernel(const float* __restrict__ gam, const float* __restrict__ bta)
{
    int wid = threadIdx.x >> 5;
    int lane = threadIdx.x & 31;
    int t = blockIdx.x * 8 + wid;
    float* row = g_xsr + (size_t)t * CC;

    float4 v0 = *(float4*)(row + lane * 8);
    float4 v1 = *(float4*)(row + lane * 8 + 4);
    float s = v0.x + v0.y + v0.z + v0.w + v1.x + v1.y + v1.z + v1.w;
#pragma unroll
    for (int o = 16; o > 0; o >>= 1) s += __shfl_xor_sync(0xFFFFFFFF, s, o);
    float mu = s * (1.f / CC);

    float d0x = v0.x - mu, d0y = v0.y - mu, d0z = v0.z - mu, d0w = v0.w - mu;
    float d1x = v1.x - mu, d1y = v1.y - mu, d1z = v1.z - mu, d1w = v1.w - mu;
    float vs = d0x * d0x + d0y * d0y + d0z * d0z + d0w * d0w
             + d1x * d1x + d1y * d1y + d1z * d1z + d1w * d1w;
#pragma unroll
    for (int o = 16; o > 0; o >>= 1) vs += __shfl_xor_sync(0xFFFFFFFF, vs, o);
    float rsig = rsqrtf(vs * (1.f / CC) + EPS);

    const float4 gm0 = *(const float4*)(gam + lane * 8);
    const float4 gm1 = *(const float4*)(gam + lane * 8 + 4);
    const float4 bt0 = *(const float4*)(bta + lane * 8);
    const float4 bt1 = *(const float4*)(bta + lane * 8 + 4);
    float4 o0 = make_float4(d0x * rsig * gm0.x + bt0.x, d0y * rsig * gm0.y + bt0.y,
                            d0z * rsig * gm0.z + bt0.z, d0w * rsig * gm0.w + bt0.w);
    float4 o1 = make_float4(d1x * rsig * gm1.x + bt1.x, d1y * rsig * gm1.y + bt1.y,
                            d1z * rsig * gm1.z + bt1.z, d1w * rsig * gm1.w + bt1.w);
    *(float4*)(row + lane * 8) = o0;
    *(float4*)(row + lane * 8 + 4) = o1;
}

// ---------------- fp16 flash attention (all-half I/O, ldmatrix frags) ----------------
#define TKV 64

__global__ void __launch_bounds__(256) attn_fa()
{
    __shared__ __half sK[TKV * KP];
    __shared__ __half sV[TKV * KP];

    const int tid = threadIdx.x;
    const int lane = tid & 31;
    const int wid = tid >> 5;
    const int g = lane >> 2;
    const int t4 = lane & 3;

    const int b = blockIdx.z;
    const int h = blockIdx.y;
    const int q0 = blockIdx.x * 128 + wid * 16;

    // Q already pre-scaled by scale*log2e at projection epilogue
    uint32_t aq[2][4];
    {
        const __half* qr = g_q16 + ((size_t)(b * NN + q0 + g)) * CC + h * HD;
        const __half* qr8 = qr + 8 * CC;
#pragma unroll
        for (int ks = 0; ks < 2; ks++) {
            aq[ks][0] = *(const uint32_t*)(qr + ks * 16 + 2 * t4);
            aq[ks][1] = *(const uint32_t*)(qr8 + ks * 16 + 2 * t4);
            aq[ks][2] = *(const uint32_t*)(qr + ks * 16 + 2 * t4 + 8);
            aq[ks][3] = *(const uint32_t*)(qr8 + ks * 16 + 2 * t4 + 8);
        }
    }

    float m[2] = {-1e30f, -1e30f};
    float l[2] = {0.f, 0.f};
    float o[4][4];
#pragma unroll
    for (int i = 0; i < 4; i++)
#pragma unroll
        for (int j = 0; j < 4; j++) o[i][j] = 0.f;

    const uint32_t sKu = smem_u32(sK);
    const uint32_t sVu = smem_u32(sV);
    const uint32_t kRow = (uint32_t)(((lane & 7) + (lane >> 4) * 8) * KP + ((lane >> 3) & 1) * 8);
    const uint32_t vRow = (uint32_t)((lane & 15) * KP + (lane >> 4) * 8);

    const int lr = tid >> 2;       // kv row 0..63
    const int lq = tid & 3;        // 8-half chunk

    for (int t0 = 0; t0 < NKV; t0 += TKV) {
        {
            const __half* src = g_kv16 + ((size_t)(b * NKV + t0 + lr)) * 512 + h * HD + lq * 8;
            *(uint4*)&sK[lr * KP + lq * 8] = *(const uint4*)src;
            *(uint4*)&sV[lr * KP + lq * 8] = *(const uint4*)(src + 256);
        }
        __syncthreads();

        // S = Q K^T : 8 n-tiles via 4 npair x 2 ks ldmatrix.x4
        float c[8][4];
#pragma unroll
        for (int nt = 0; nt < 8; nt++) {
            c[nt][0] = 0.f; c[nt][1] = 0.f; c[nt][2] = 0.f; c[nt][3] = 0.f;
        }
#pragma unroll
        for (int j = 0; j < 4; j++) {
#pragma unroll
            for (int ks = 0; ks < 2; ks++) {
                uint32_t bk[4];
                ldsm4(bk, sKu + (kRow + j * 16 * KP + ks * 16) * 2);
                mma_f16(c[2 * j], aq[ks], bk);
                mma_f16(c[2 * j + 1], aq[ks], bk + 2);
            }
        }

        // online softmax (base-2)
#pragma unroll
        for (int rh = 0; rh < 2; rh++) {
            float mx = c[0][2 * rh];
#pragma unroll
            for (int nt = 0; nt < 8; nt++)
                mx = fmaxf(mx, fmaxf(c[nt][2 * rh], c[nt][2 * rh + 1]));
            mx = fmaxf(mx, __shfl_xor_sync(0xFFFFFFFF, mx, 1));
            mx = fmaxf(mx, __shfl_xor_sync(0xFFFFFFFF, mx, 2));
            float mnew = fmaxf(m[rh], mx);
            float alpha = ex2f(m[rh] - mnew);
#pragma unroll
            for (int i = 0; i < 4; i++) {
                o[i][2 * rh] *= alpha;
                o[i][2 * rh + 1] *= alpha;
            }
            float sum = 0.f;
#pragma unroll
            for (int nt = 0; nt < 8; nt++) {
                float p0 = ex2f(c[nt][2 * rh] - mnew);
                float p1 = ex2f(c[nt][2 * rh + 1] - mnew);
                c[nt][2 * rh] = p0;
                c[nt][2 * rh + 1] = p1;
                sum += p0 + p1;
            }
            sum += __shfl_xor_sync(0xFFFFFFFF, sum, 1);
            sum += __shfl_xor_sync(0xFFFFFFFF, sum, 2);
            l[rh] = l[rh] * alpha + sum;
            m[rh] = mnew;
        }

        // pack P to fp16 a-frags (C layout == A layout)
        uint32_t ap[4][4];
#pragma unroll
        for (int k = 0; k < 4; k++) {
            __half2 p0 = __floats2half2_rn(c[2 * k][0], c[2 * k][1]);
            __half2 p1 = __floats2half2_rn(c[2 * k][2], c[2 * k][3]);
            __half2 p2 = __floats2half2_rn(c[2 * k + 1][0], c[2 * k + 1][1]);
            __half2 p3 = __floats2half2_rn(c[2 * k + 1][2], c[2 * k + 1][3]);
            ap[k][0] = *(uint32_t*)&p0;
            ap[k][1] = *(uint32_t*)&p1;
            ap[k][2] = *(uint32_t*)&p2;
            ap[k][3] = *(uint32_t*)&p3;
        }

        // O += P V : V b-frags via ldmatrix.trans from row-major sV
#pragma unroll
        for (int k = 0; k < 4; k++) {
#pragma unroll
            for (int j = 0; j < 2; j++) {
                uint32_t bv[4];
                ldsm4t(bv, sVu + (vRow + k * 16 * KP + j * 16) * 2);
                mma_f16(o[2 * j], ap[k], bv);
                mma_f16(o[2 * j + 1], ap[k], bv + 2);
            }
        }
        __syncthreads();
    }

    float inv0 = 1.f / l[0];
    float inv1 = 1.f / l[1];
    __half* out0 = g_at16 + ((size_t)(b * NN + q0 + g)) * CC + h * HD;
    __half* out8 = out0 + 8 * CC;
#pragma unroll
    for (int nt = 0; nt < 4; nt++) {
        int cidx = nt * 8 + 2 * t4;
        __half2 h0 = __floats2half2_rn(o[nt][0] * inv0, o[nt][1] * inv0);
        __half2 h1 = __floats2half2_rn(o[nt][2] * inv1, o[nt][3] * inv1);
        *(uint32_t*)(out0 + cidx) = *(uint32_t*)&h0;
        *(uint32_t*)(out8 + cidx) = *(uint32_t*)&h1;
    }
}

// ---------------- launch ----------------
extern "C" void kernel_launch(void* const* d_in, const int* in_sizes, int n_in,
                              void* d_out, int out_size)
{
    const float* x      = (const float*)d_in[0];
    const float* q_w    = (const float*)d_in[1];
    const float* q_b    = (const float*)d_in[2];
    const float* kv_w   = (const float*)d_in[3];
    const float* kv_b   = (const float*)d_in[4];
    const float* sr_w   = (const float*)d_in[5];
    const float* sr_b   = (const float*)d_in[6];
    const float* ln_g   = (const float*)d_in[7];
    const float* ln_b   = (const float*)d_in[8];
    const float* proj_w = (const float*)d_in[9];
    const float* proj_b = (const float*)d_in[10];
    float* out = (float*)d_out;

    __half* gq  = nullptr; cudaGetSymbolAddress((void**)&gq,  g_q16);
    float*  gxs = nullptr; cudaGetSymbolAddress((void**)&gxs, g_xsr);
    __half* gkv = nullptr; cudaGetSymbolAddress((void**)&gkv, g_kv16);
    __half* gat = nullptr; cudaGetSymbolAddress((void**)&gat, g_at16);
    __half* gw  = nullptr; cudaGetSymbolAddress((void**)&gw,  g_w16);

    const float qscale = 0.17677669529663687f * 1.4426950408889634f;

    // 0) convert all weights to fp16 (sr_w reordered)
    prep_w<<<W16_TOTAL / 256, 256>>>(q_w, kv_w, sr_w, proj_w);

    // 1) Q projection -> half, pre-scaled
    gemm_h<false, false, true><<<dim3(2, 128), 256>>>(x, gw + QW_OFF, q_b, gq,
                                                      BB * NN, CC, CC, qscale);

    // 2) conv as gathered GEMM -> fp32 (feeds LN)
    gemm_h<false, true, false><<<dim3(2, 32), 256>>>(x, gw + SRW_OFF, sr_b, gxs,
                                                     BB * NKV, CC, 1024, 1.f);

    // 3) LayerNorm in place (warp per token)
    ln_kernel<<<BB * NKV / 8, 256>>>(ln_g, ln_b);

    // 4) KV projection -> half
    gemm_h<false, false, true><<<dim3(4, 32), 256>>>(gxs, gw + KV_OFF, kv_b, gkv,
                                                     BB * NKV, 512, CC, 1.f);

    // 5) flash attention (half in, half out)
    attn_fa<<<dim3(NN / 128, HEADS, BB), 256>>>();

    // 6) output projection (half A) -> fp32 out
    gemm_h<true, false, false><<<dim3(2, 128), 256>>>(gat, gw + PJ_OFF, proj_b, out,
                                                      BB * NN, CC, CC, 1.f);
}

// round 6
// speedup vs baseline: 6.5863x; 1.1878x over previous
#include <cuda_runtime.h>
#include <cuda_fp16.h>
#include <math.h>
#include <cstdint>

// ---------------- constants ----------------
#define BB 4
#define NN 4096
#define CC 256
#define HEADS 8
#define HD 32
#define NKV 1024
#define EPS 1e-5f

#define QW_OFF 0
#define KV_OFF 65536
#define SRW_OFF 196608
#define PJ_OFF 458752
#define W16_TOTAL 524288

// ---------------- scratch (device globals) ----------------
__device__ __half g_q16[BB * NN * CC];       //  8 MB (pre-scaled by scale*log2e)
__device__ float  g_xsr[BB * NKV * CC];      //  4 MB (conv output, raw + bias)
__device__ float2 g_stats[BB * NKV];         //  32 KB (mu, rstd per kv token)
__device__ __half g_kv16[BB * NKV * 512];    //  4 MB
__device__ __half g_at16[BB * NN * CC];      //  8 MB
__device__ __half g_w16[W16_TOTAL];          //  1 MB  all weights fp16

// ---------------- PTX helpers ----------------
__device__ __forceinline__ uint32_t smem_u32(const void* p) {
    uint32_t a;
    asm("{ .reg .u64 t; cvta.to.shared.u64 t, %1; cvt.u32.u64 %0, t; }" : "=r"(a) : "l"(p));
    return a;
}
__device__ __forceinline__ void ldsm4(uint32_t* r, uint32_t addr) {
    asm volatile("ldmatrix.sync.aligned.m8n8.x4.shared.b16 {%0,%1,%2,%3}, [%4];"
        : "=r"(r[0]), "=r"(r[1]), "=r"(r[2]), "=r"(r[3]) : "r"(addr));
}
__device__ __forceinline__ void ldsm4t(uint32_t* r, uint32_t addr) {
    asm volatile("ldmatrix.sync.aligned.m8n8.x4.trans.shared.b16 {%0,%1,%2,%3}, [%4];"
        : "=r"(r[0]), "=r"(r[1]), "=r"(r[2]), "=r"(r[3]) : "r"(addr));
}
__device__ __forceinline__ void mma_f16(float* d, const uint32_t* a, const uint32_t* b) {
    asm volatile(
        "mma.sync.aligned.m16n8k16.row.col.f32.f16.f16.f32 "
        "{%0,%1,%2,%3}, {%4,%5,%6,%7}, {%8,%9}, {%0,%1,%2,%3};\n"
        : "+f"(d[0]), "+f"(d[1]), "+f"(d[2]), "+f"(d[3])
        : "r"(a[0]), "r"(a[1]), "r"(a[2]), "r"(a[3]), "r"(b[0]), "r"(b[1]));
}
__device__ __forceinline__ float ex2f(float x) {
    float r; asm("ex2.approx.f32 %0, %1;" : "=f"(r) : "f"(x)); return r;
}
__device__ __forceinline__ void cpa16(uint32_t dst, const void* src) {
    asm volatile("cp.async.cg.shared.global [%0], [%1], 16;" :: "r"(dst), "l"(src) : "memory");
}
#define CPA_COMMIT() asm volatile("cp.async.commit_group;" ::: "memory")
#define CPA_WAIT(n)  asm volatile("cp.async.wait_group %0;" :: "n"(n) : "memory")

// ---------------- weight prep: fp32 -> fp16, sr_w reordered ----------------
__global__ void prep_w(const float* __restrict__ qw, const float* __restrict__ kvw,
                       const float* __restrict__ srw, const float* __restrict__ pjw)
{
    int idx = blockIdx.x * blockDim.x + threadIdx.x;
    float v;
    if (idx < KV_OFF) {
        v = qw[idx];
    } else if (idx < SRW_OFF) {
        v = kvw[idx - KV_OFF];
    } else if (idx < PJ_OFF) {
        int r = idx - SRW_OFF;
        int co = r >> 10;
        int khw = (r >> 8) & 3;
        int ci = r & 255;
        v = srw[co * 1024 + ci * 4 + khw];
    } else {
        v = pjw[idx - PJ_OFF];
    }
    g_w16[idx] = __float2half_rn(v);
}

// ---------------- per-row stats (mean, rstd) of g_xsr ----------------
__global__ void stats_kernel()
{
    int wid = threadIdx.x >> 5;
    int lane = threadIdx.x & 31;
    int t = blockIdx.x * 8 + wid;
    const float* row = g_xsr + (size_t)t * CC;

    float4 v0 = *(const float4*)(row + lane * 8);
    float4 v1 = *(const float4*)(row + lane * 8 + 4);
    float s = v0.x + v0.y + v0.z + v0.w + v1.x + v1.y + v1.z + v1.w;
#pragma unroll
    for (int o = 16; o > 0; o >>= 1) s += __shfl_xor_sync(0xFFFFFFFF, s, o);
    float mu = s * (1.f / CC);

    float d0x = v0.x - mu, d0y = v0.y - mu, d0z = v0.z - mu, d0w = v0.w - mu;
    float d1x = v1.x - mu, d1y = v1.y - mu, d1z = v1.z - mu, d1w = v1.w - mu;
    float vs = d0x * d0x + d0y * d0y + d0z * d0z + d0w * d0w
             + d1x * d1x + d1y * d1y + d1z * d1z + d1w * d1w;
#pragma unroll
    for (int o = 16; o > 0; o >>= 1) vs += __shfl_xor_sync(0xFFFFFFFF, vs, o);
    float rsig = rsqrtf(vs * (1.f / CC) + EPS);

    if (lane == 0) g_stats[t] = make_float2(mu, rsig);
}

// ---------------- fp16 warp-mma GEMM: C[M,N] = A[M,K] @ B[N,K]^T + bias, *oscale ----------------
// Block MT x 128, 8 warps (2 x 4), warp (MT/2) x 32, K-stage 32, double-buffered smem, KP=40.
#define KP 40

template <int MT, bool A_HALF, bool GATHER, bool NORM, bool OUT_HALF>
__global__ void __launch_bounds__(256) gemm_h(const void* __restrict__ Av,
                                              const __half* __restrict__ B,
                                              const float* __restrict__ bias,
                                              void* __restrict__ Cv,
                                              int M, int N, int K, float oscale,
                                              const float* __restrict__ nrm_g,
                                              const float* __restrict__ nrm_b)
{
    constexpr int IT = MT / 32;              // m16-tiles per warp
    constexpr int AROWS = (MT == 128) ? 2 : 1;

    __shared__ __half sA[2][MT * KP];
    __shared__ __half sB[2][128 * KP];

    const int tid = threadIdx.x;
    const int lane = tid & 31;
    const int wid = tid >> 5;
    const int wm = wid >> 2;
    const int wn = wid & 3;
    const int rowBase = blockIdx.y * MT;
    const int colBase = blockIdx.x * 128;
    const int g = lane >> 2;
    const int t4 = lane & 3;

    // A loader: AROWS rows per thread, one 8-half chunk each
    const int ar = tid >> 2;       // 0..63
    const int ac = tid & 3;        // chunk
    // B loader: 128 rows, 2 chunks of 16 halves
    const int br = tid >> 1;
    const int bp = tid & 1;

    const int S = K >> 5;

    float4 raf[AROWS][2];
    uint4 rah[AROWS];
    uint4 rbh[2];
    float2 st[AROWS];
    if (NORM) {
#pragma unroll
        for (int pp = 0; pp < AROWS; pp++)
            st[pp] = g_stats[rowBase + pp * 64 + ar];
    }

    auto issue_loads = [&](int s) {
        int k0 = s << 5;
#pragma unroll
        for (int pp = 0; pp < AROWS; pp++) {
            int row = pp * 64 + ar;
            if (A_HALF) {
                const __half* Ah = (const __half*)Av;
                rah[pp] = *(const uint4*)(Ah + (size_t)(rowBase + row) * K + k0 + ac * 8);
            } else {
                const float* Af;
                if (GATHER) {
                    int grow = rowBase + row;
                    int khw = k0 >> 8;
                    int ci0 = (k0 & 255) + ac * 8;
                    int bI = grow >> 10, tt = grow & 1023;
                    int ii = tt >> 5, jj = tt & 31;
                    int y = 2 * ii + (khw >> 1), xx = 2 * jj + (khw & 1);
                    Af = (const float*)Av + ((size_t)((bI << 12) + y * 64 + xx)) * 256 + ci0;
                } else {
                    Af = (const float*)Av + (size_t)(rowBase + row) * K + k0 + ac * 8;
                }
                raf[pp][0] = ((const float4*)Af)[0];
                raf[pp][1] = ((const float4*)Af)[1];
                if (NORM) {
                    float mu = st[pp].x, rs = st[pp].y;
                    const float4 g0 = *(const float4*)(nrm_g + k0 + ac * 8);
                    const float4 g1 = *(const float4*)(nrm_g + k0 + ac * 8 + 4);
                    const float4 b0 = *(const float4*)(nrm_b + k0 + ac * 8);
                    const float4 b1 = *(const float4*)(nrm_b + k0 + ac * 8 + 4);
                    raf[pp][0].x = (raf[pp][0].x - mu) * rs * g0.x + b0.x;
                    raf[pp][0].y = (raf[pp][0].y - mu) * rs * g0.y + b0.y;
                    raf[pp][0].z = (raf[pp][0].z - mu) * rs * g0.z + b0.z;
                    raf[pp][0].w = (raf[pp][0].w - mu) * rs * g0.w + b0.w;
                    raf[pp][1].x = (raf[pp][1].x - mu) * rs * g1.x + b1.x;
                    raf[pp][1].y = (raf[pp][1].y - mu) * rs * g1.y + b1.y;
                    raf[pp][1].z = (raf[pp][1].z - mu) * rs * g1.z + b1.z;
                    raf[pp][1].w = (raf[pp][1].w - mu) * rs * g1.w + b1.w;
                }
            }
        }
        const uint4* bs = (const uint4*)(B + (size_t)(colBase + br) * K + k0 + bp * 16);
        rbh[0] = bs[0]; rbh[1] = bs[1];
    };

    auto store_stage = [&](int buf) {
#pragma unroll
        for (int pp = 0; pp < AROWS; pp++) {
            int row = pp * 64 + ar;
            __half* dA = &sA[buf][row * KP + ac * 8];
            if (A_HALF) {
                *(uint4*)dA = rah[pp];
            } else {
                __half2* d2 = (__half2*)dA;
                d2[0] = __floats2half2_rn(raf[pp][0].x, raf[pp][0].y);
                d2[1] = __floats2half2_rn(raf[pp][0].z, raf[pp][0].w);
                d2[2] = __floats2half2_rn(raf[pp][1].x, raf[pp][1].y);
                d2[3] = __floats2half2_rn(raf[pp][1].z, raf[pp][1].w);
            }
        }
        __half* dB = &sB[buf][br * KP + bp * 16];
        ((uint4*)dB)[0] = rbh[0];
        ((uint4*)dB)[1] = rbh[1];
    };

    float acc[IT][4][4];
#pragma unroll
    for (int i = 0; i < IT; i++)
#pragma unroll
        for (int j = 0; j < 4; j++)
#pragma unroll
            for (int q = 0; q < 4; q++) acc[i][j][q] = 0.f;

    const uint32_t sAu = smem_u32(sA);
    const uint32_t sBu = smem_u32(sB);
    const uint32_t aRow = (uint32_t)((wm * (MT / 2) + (lane & 15)) * KP + (lane >> 4) * 8);
    const uint32_t bRow = (uint32_t)((wn * 32 + (lane & 7) + (lane >> 4) * 8) * KP + ((lane >> 3) & 1) * 8);

    issue_loads(0);
    store_stage(0);
    __syncthreads();

    for (int s = 0; s < S; s++) {
        int buf = s & 1;
        if (s + 1 < S) issue_loads(s + 1);

        const uint32_t baseA = sAu + buf * (MT * KP * 2);
        const uint32_t baseB = sBu + buf * (128 * KP * 2);
#pragma unroll
        for (int ks = 0; ks < 2; ks++) {
            uint32_t a[IT][4];
#pragma unroll
            for (int i = 0; i < IT; i++)
                ldsm4(a[i], baseA + (aRow + i * 16 * KP + ks * 16) * 2);
#pragma unroll
            for (int j = 0; j < 2; j++) {
                uint32_t bf[4];
                ldsm4(bf, baseB + (bRow + j * 16 * KP + ks * 16) * 2);
#pragma unroll
                for (int i = 0; i < IT; i++) {
                    mma_f16(acc[i][2 * j], a[i], bf);
                    mma_f16(acc[i][2 * j + 1], a[i], bf + 2);
                }
            }
        }

        if (s + 1 < S) store_stage(buf ^ 1);
        __syncthreads();
    }

#pragma unroll
    for (int i = 0; i < IT; i++) {
#pragma unroll
        for (int jt = 0; jt < 4; jt++) {
            int rr = rowBase + wm * (MT / 2) + i * 16 + g;
            int cc = colBase + wn * 32 + jt * 8 + t4 * 2;
            float b0 = bias[cc], b1 = bias[cc + 1];
            float v00 = (acc[i][jt][0] + b0) * oscale;
            float v01 = (acc[i][jt][1] + b1) * oscale;
            float v10 = (acc[i][jt][2] + b0) * oscale;
            float v11 = (acc[i][jt][3] + b1) * oscale;
            if (OUT_HALF) {
                __half* C = (__half*)Cv;
                __half2 h0 = __floats2half2_rn(v00, v01);
                __half2 h1 = __floats2half2_rn(v10, v11);
                *(uint32_t*)&C[(size_t)rr * N + cc] = *(uint32_t*)&h0;
                *(uint32_t*)&C[(size_t)(rr + 8) * N + cc] = *(uint32_t*)&h1;
            } else {
                float* C = (float*)Cv;
                *(float2*)&C[(size_t)rr * N + cc] = make_float2(v00, v01);
                *(float2*)&C[(size_t)(rr + 8) * N + cc] = make_float2(v10, v11);
            }
        }
    }
}

// ---------------- fp16 flash attention: cp.async double-buffered K/V ----------------
#define TKV 64
#define NT_KV (NKV / TKV)

__global__ void __launch_bounds__(256) attn_fa()
{
    __shared__ __half sK[2][TKV * KP];
    __shared__ __half sV[2][TKV * KP];

    const int tid = threadIdx.x;
    const int lane = tid & 31;
    const int wid = tid >> 5;
    const int g = lane >> 2;
    const int t4 = lane & 3;

    const int b = blockIdx.z;
    const int h = blockIdx.y;
    const int q0 = blockIdx.x * 128 + wid * 16;

    uint32_t aq[2][4];
    {
        const __half* qr = g_q16 + ((size_t)(b * NN + q0 + g)) * CC + h * HD;
        const __half* qr8 = qr + 8 * CC;
#pragma unroll
        for (int ks = 0; ks < 2; ks++) {
            aq[ks][0] = *(const uint32_t*)(qr + ks * 16 + 2 * t4);
            aq[ks][1] = *(const uint32_t*)(qr8 + ks * 16 + 2 * t4);
            aq[ks][2] = *(const uint32_t*)(qr + ks * 16 + 2 * t4 + 8);
            aq[ks][3] = *(const uint32_t*)(qr8 + ks * 16 + 2 * t4 + 8);
        }
    }

    float m[2] = {-1e30f, -1e30f};
    float l[2] = {0.f, 0.f};
    float o[4][4];
#pragma unroll
    for (int i = 0; i < 4; i++)
#pragma unroll
        for (int j = 0; j < 4; j++) o[i][j] = 0.f;

    const uint32_t sKu = smem_u32(sK);
    const uint32_t sVu = smem_u32(sV);
    const uint32_t kRow = (uint32_t)(((lane & 7) + (lane >> 4) * 8) * KP + ((lane >> 3) & 1) * 8);
    const uint32_t vRow = (uint32_t)((lane & 15) * KP + (lane >> 4) * 8);

    const int lr = tid >> 2;       // kv row 0..63
    const int lq = tid & 3;        // 8-half chunk

    auto load_tile = [&](int t0, int buf) {
        const __half* src = g_kv16 + ((size_t)(b * NKV + t0 + lr)) * 512 + h * HD + lq * 8;
        uint32_t off = (uint32_t)((buf * TKV * KP + lr * KP + lq * 8) * 2);
        cpa16(sKu + off, src);
        cpa16(sVu + off, src + 256);
    };

    load_tile(0, 0);
    CPA_COMMIT();

    for (int it = 0; it < NT_KV; it++) {
        int buf = it & 1;
        if (it + 1 < NT_KV) {
            load_tile((it + 1) * TKV, buf ^ 1);
            CPA_COMMIT();
            CPA_WAIT(1);
        } else {
            CPA_WAIT(0);
        }
        __syncthreads();

        const uint32_t baseK = sKu + buf * (TKV * KP * 2);
        const uint32_t baseV = sVu + buf * (TKV * KP * 2);

        // S = Q K^T
        float c[8][4];
#pragma unroll
        for (int nt = 0; nt < 8; nt++) {
            c[nt][0] = 0.f; c[nt][1] = 0.f; c[nt][2] = 0.f; c[nt][3] = 0.f;
        }
#pragma unroll
        for (int j = 0; j < 4; j++) {
#pragma unroll
            for (int ks = 0; ks < 2; ks++) {
                uint32_t bk[4];
                ldsm4(bk, baseK + (kRow + j * 16 * KP + ks * 16) * 2);
                mma_f16(c[2 * j], aq[ks], bk);
                mma_f16(c[2 * j + 1], aq[ks], bk + 2);
            }
        }

        // online softmax (base-2)
#pragma unroll
        for (int rh = 0; rh < 2; rh++) {
            float mx = c[0][2 * rh];
#pragma unroll
            for (int nt = 0; nt < 8; nt++)
                mx = fmaxf(mx, fmaxf(c[nt][2 * rh], c[nt][2 * rh + 1]));
            mx = fmaxf(mx, __shfl_xor_sync(0xFFFFFFFF, mx, 1));
            mx = fmaxf(mx, __shfl_xor_sync(0xFFFFFFFF, mx, 2));
            float mnew = fmaxf(m[rh], mx);
            float alpha = ex2f(m[rh] - mnew);
#pragma unroll
            for (int i = 0; i < 4; i++) {
                o[i][2 * rh] *= alpha;
                o[i][2 * rh + 1] *= alpha;
            }
            float sum = 0.f;
#pragma unroll
            for (int nt = 0; nt < 8; nt++) {
                float p0 = ex2f(c[nt][2 * rh] - mnew);
                float p1 = ex2f(c[nt][2 * rh + 1] - mnew);
                c[nt][2 * rh] = p0;
                c[nt][2 * rh + 1] = p1;
                sum += p0 + p1;
            }
            sum += __shfl_xor_sync(0xFFFFFFFF, sum, 1);
            sum += __shfl_xor_sync(0xFFFFFFFF, sum, 2);
            l[rh] = l[rh] * alpha + sum;
            m[rh] = mnew;
        }

        // pack P (C layout == A layout)
        uint32_t ap[4][4];
#pragma unroll
        for (int k = 0; k < 4; k++) {
            __half2 p0 = __floats2half2_rn(c[2 * k][0], c[2 * k][1]);
            __half2 p1 = __floats2half2_rn(c[2 * k][2], c[2 * k][3]);
            __half2 p2 = __floats2half2_rn(c[2 * k + 1][0], c[2 * k + 1][1]);
            __half2 p3 = __floats2half2_rn(c[2 * k + 1][2], c[2 * k + 1][3]);
            ap[k][0] = *(uint32_t*)&p0;
            ap[k][1] = *(uint32_t*)&p1;
            ap[k][2] = *(uint32_t*)&p2;
            ap[k][3] = *(uint32_t*)&p3;
        }

        // O += P V
#pragma unroll
        for (int k = 0; k < 4; k++) {
#pragma unroll
            for (int j = 0; j < 2; j++) {
                uint32_t bv[4];
                ldsm4t(bv, baseV + (vRow + k * 16 * KP + j * 16) * 2);
                mma_f16(o[2 * j], ap[k], bv);
                mma_f16(o[2 * j + 1], ap[k], bv + 2);
            }
        }
        __syncthreads();
    }

    float inv0 = 1.f / l[0];
    float inv1 = 1.f / l[1];
    __half* out0 = g_at16 + ((size_t)(b * NN + q0 + g)) * CC + h * HD;
    __half* out8 = out0 + 8 * CC;
#pragma unroll
    for (int nt = 0; nt < 4; nt++) {
        int cidx = nt * 8 + 2 * t4;
        __half2 h0 = __floats2half2_rn(o[nt][0] * inv0, o[nt][1] * inv0);
        __half2 h1 = __floats2half2_rn(o[nt][2] * inv1, o[nt][3] * inv1);
        *(uint32_t*)(out0 + cidx) = *(uint32_t*)&h0;
        *(uint32_t*)(out8 + cidx) = *(uint32_t*)&h1;
    }
}

// ---------------- launch ----------------
extern "C" void kernel_launch(void* const* d_in, const int* in_sizes, int n_in,
                              void* d_out, int out_size)
{
    const float* x      = (const float*)d_in[0];
    const float* q_w    = (const float*)d_in[1];
    const float* q_b    = (const float*)d_in[2];
    const float* kv_w   = (const float*)d_in[3];
    const float* kv_b   = (const float*)d_in[4];
    const float* sr_w   = (const float*)d_in[5];
    const float* sr_b   = (const float*)d_in[6];
    const float* ln_g   = (const float*)d_in[7];
    const float* ln_b   = (const float*)d_in[8];
    const float* proj_w = (const float*)d_in[9];
    const float* proj_b = (const float*)d_in[10];
    float* out = (float*)d_out;

    __half* gq  = nullptr; cudaGetSymbolAddress((void**)&gq,  g_q16);
    float*  gxs = nullptr; cudaGetSymbolAddress((void**)&gxs, g_xsr);
    __half* gkv = nullptr; cudaGetSymbolAddress((void**)&gkv, g_kv16);
    __half* gat = nullptr; cudaGetSymbolAddress((void**)&gat, g_at16);
    __half* gw  = nullptr; cudaGetSymbolAddress((void**)&gw,  g_w16);

    const float qscale = 0.17677669529663687f * 1.4426950408889634f;

    // 0) weights -> fp16 (sr_w reordered)
    prep_w<<<W16_TOTAL / 256, 256>>>(q_w, kv_w, sr_w, proj_w);

    // 1) Q projection -> half, pre-scaled
    gemm_h<128, false, false, false, true><<<dim3(2, 128), 256>>>(
        x, gw + QW_OFF, q_b, gq, BB * NN, CC, CC, qscale, nullptr, nullptr);

    // 2) conv as gathered GEMM -> fp32 raw (bias included)
    gemm_h<64, false, true, false, false><<<dim3(2, 64), 256>>>(
        x, gw + SRW_OFF, sr_b, gxs, BB * NKV, CC, 1024, 1.f, nullptr, nullptr);

    // 3) per-row LN stats
    stats_kernel<<<BB * NKV / 8, 256>>>();

    // 4) KV projection with fused LayerNorm on A -> half
    gemm_h<64, false, false, true, true><<<dim3(4, 64), 256>>>(
        gxs, gw + KV_OFF, kv_b, gkv, BB * NKV, 512, CC, 1.f, ln_g, ln_b);

    // 5) flash attention (cp.async double-buffered)
    attn_fa<<<dim3(NN / 128, HEADS, BB), 256>>>();

    // 6) output projection (half A) -> fp32 out
    gemm_h<128, true, false, false, false><<<dim3(2, 128), 256>>>(
        gat, gw + PJ_OFF, proj_b, out, BB * NN, CC, CC, 1.f, nullptr, nullptr);
}